// round 1
// baseline (speedup 1.0000x reference)
#include <cuda_runtime.h>
#include <cstddef>

// Problem constants (from reference):
//   pix_to_face : [N,H,W,K]      int32,  K = 4
//   bary_coords : [N,H,W,K,3]    float32
//   faces       : [F,3]          int32,  F = 200000
//   verts_colors: [V,3]          float32, V = 100000
//   output      : [N,H,W,3]      float32  (sample K=0 only)

#define KSAMP 4
#define PIX_PER_THREAD 4

__global__ void __launch_bounds__(256)
unlit_shader_kernel(const int*   __restrict__ pix_to_face,
                    const float* __restrict__ bary,
                    const int*   __restrict__ faces,
                    const float* __restrict__ verts,
                    float*       __restrict__ out,
                    int npix)
{
    const int t  = blockIdx.x * blockDim.x + threadIdx.x;
    const int p0 = t * PIX_PER_THREAD;
    if (p0 >= npix) return;

    // Fast path: all 4 pixels in range (npix = 2M is divisible by 4, but keep a tail guard).
    const bool full = (p0 + PIX_PER_THREAD <= npix);

    // 1) Front-batch the 4 face-index loads (MLP for the long-scoreboard chain).
    int f[PIX_PER_THREAD];
#pragma unroll
    for (int j = 0; j < PIX_PER_THREAD; ++j) {
        const int p = p0 + j;
        f[j] = (full || p < npix) ? __ldg(pix_to_face + (size_t)p * KSAMP) : -1;
    }

    // 2) Front-batch the 4 barycentric float4 loads (offset 48*p is 16B-aligned;
    //    reads 16B where only 12B are K=0's weights — same sectors either way).
    float4 w[PIX_PER_THREAD];
#pragma unroll
    for (int j = 0; j < PIX_PER_THREAD; ++j) {
        const int p = p0 + j;
        if (f[j] >= 0) {
            w[j] = __ldg(reinterpret_cast<const float4*>(bary + (size_t)p * (KSAMP * 3)));
        } else {
            w[j] = make_float4(0.f, 0.f, 0.f, 0.f);
        }
    }

    // 3) Gather vertex indices for all 4 pixels (independent L2 gathers in flight).
    int v0[PIX_PER_THREAD], v1[PIX_PER_THREAD], v2[PIX_PER_THREAD];
#pragma unroll
    for (int j = 0; j < PIX_PER_THREAD; ++j) {
        const size_t fb = (size_t)(f[j] >= 0 ? f[j] : 0) * 3;
        v0[j] = __ldg(faces + fb + 0);
        v1[j] = __ldg(faces + fb + 1);
        v2[j] = __ldg(faces + fb + 2);
    }

    // 4) Gather colors + weighted sum.
    float o[PIX_PER_THREAD * 3];
#pragma unroll
    for (int j = 0; j < PIX_PER_THREAD; ++j) {
        if (f[j] >= 0) {
            const float* c0 = verts + (size_t)v0[j] * 3;
            const float* c1 = verts + (size_t)v1[j] * 3;
            const float* c2 = verts + (size_t)v2[j] * 3;
            const float wx = w[j].x, wy = w[j].y, wz = w[j].z;
            o[j * 3 + 0] = wx * __ldg(c0 + 0) + wy * __ldg(c1 + 0) + wz * __ldg(c2 + 0);
            o[j * 3 + 1] = wx * __ldg(c0 + 1) + wy * __ldg(c1 + 1) + wz * __ldg(c2 + 1);
            o[j * 3 + 2] = wx * __ldg(c0 + 2) + wy * __ldg(c1 + 2) + wz * __ldg(c2 + 2);
        } else {
            o[j * 3 + 0] = 0.f;
            o[j * 3 + 1] = 0.f;
            o[j * 3 + 2] = 0.f;
        }
    }

    // 5) Store: 12 contiguous floats per thread -> 3x STG.128, fully coalesced.
    float* ob = out + (size_t)p0 * 3;
    if (full) {
        float4* o4 = reinterpret_cast<float4*>(ob);
        o4[0] = make_float4(o[0], o[1],  o[2],  o[3]);
        o4[1] = make_float4(o[4], o[5],  o[6],  o[7]);
        o4[2] = make_float4(o[8], o[9],  o[10], o[11]);
    } else {
#pragma unroll
        for (int j = 0; j < PIX_PER_THREAD; ++j) {
            const int p = p0 + j;
            if (p < npix) {
                ob[j * 3 + 0] = o[j * 3 + 0];
                ob[j * 3 + 1] = o[j * 3 + 1];
                ob[j * 3 + 2] = o[j * 3 + 2];
            }
        }
    }
}

extern "C" void kernel_launch(void* const* d_in, const int* in_sizes, int n_in,
                              void* d_out, int out_size)
{
    const int*   pix_to_face = (const int*)  d_in[0];
    const float* bary        = (const float*)d_in[1];
    const int*   faces       = (const int*)  d_in[2];
    const float* verts       = (const float*)d_in[3];
    float*       out         = (float*)      d_out;

    const int npix     = in_sizes[0] / KSAMP;               // N*H*W
    const int nthreads = (npix + PIX_PER_THREAD - 1) / PIX_PER_THREAD;
    const int block    = 256;
    const int grid     = (nthreads + block - 1) / block;

    unlit_shader_kernel<<<grid, block>>>(pix_to_face, bary, faces, verts, out, npix);
}

// round 2
// speedup vs baseline: 1.2296x; 1.2296x over previous
#include <cuda_runtime.h>
#include <cstddef>

// Problem constants (from reference):
//   pix_to_face : [N,H,W,K]      int32,  K = 4
//   bary_coords : [N,H,W,K,3]    float32
//   faces       : [F,3]          int32,  F = 200000
//   verts_colors: [V,3]          float32, V = 100000
//   output      : [N,H,W,3]      float32  (sample K=0 only)

#define KSAMP 4
#define PIX_PER_THREAD 4
#define F_MAX 200000

// Scratch: per-face per-vertex color, padded to float4 for aligned 16B gathers.
// 200000 * 3 * 16B = 9.6 MB -> L2-resident during the main kernel.
__device__ float4 g_face_colors[F_MAX * 3];

// ---------------------------------------------------------------------------
// Prepro: face_colors[i] = verts_colors[faces[i]]  (i over F*3 face-vertices)
// ---------------------------------------------------------------------------
__global__ void __launch_bounds__(256)
build_face_colors(const int*   __restrict__ faces,
                  const float* __restrict__ verts,
                  int nfv)
{
    const int i = blockIdx.x * blockDim.x + threadIdx.x;
    if (i >= nfv) return;
    const int v = __ldg(faces + i);
    const float c0 = __ldg(verts + (size_t)v * 3 + 0);
    const float c1 = __ldg(verts + (size_t)v * 3 + 1);
    const float c2 = __ldg(verts + (size_t)v * 3 + 2);
    g_face_colors[i] = make_float4(c0, c1, c2, 0.0f);
}

// ---------------------------------------------------------------------------
// Main shader: 4 pixels/thread, single gather level into g_face_colors.
// ---------------------------------------------------------------------------
__global__ void __launch_bounds__(256)
unlit_shader_kernel(const int*   __restrict__ pix_to_face,
                    const float* __restrict__ bary,
                    float*       __restrict__ out,
                    int npix)
{
    const int t  = blockIdx.x * blockDim.x + threadIdx.x;
    const int p0 = t * PIX_PER_THREAD;
    if (p0 >= npix) return;
    const bool full = (p0 + PIX_PER_THREAD <= npix);

    // 1) pix_to_face: vectorized int4 (16B aligned: offset = 16B * p). We only
    //    need .x (sample K=0) but the sectors are fetched either way; the
    //    vector form is 1 coalesced wavefront instead of stride-16B replays.
    int f[PIX_PER_THREAD];
#pragma unroll
    for (int j = 0; j < PIX_PER_THREAD; ++j) {
        const int p = p0 + j;
        if (full || p < npix) {
            const int4 s = __ldcs(reinterpret_cast<const int4*>(pix_to_face) + p);
            f[j] = s.x;
        } else {
            f[j] = -1;
        }
    }

    // 2) bary weights: float4 at 48B stride (16B aligned). Streaming hint.
    float4 w[PIX_PER_THREAD];
#pragma unroll
    for (int j = 0; j < PIX_PER_THREAD; ++j) {
        const int p = p0 + j;
        w[j] = (f[j] >= 0)
             ? __ldcs(reinterpret_cast<const float4*>(bary + (size_t)p * (KSAMP * 3)))
             : make_float4(0.f, 0.f, 0.f, 0.f);
    }

    // 3) Single-level gather: 3x float4 per pixel from the L2-resident table,
    //    all 12 loads independent -> deep MLP.
    float4 c0[PIX_PER_THREAD], c1[PIX_PER_THREAD], c2[PIX_PER_THREAD];
#pragma unroll
    for (int j = 0; j < PIX_PER_THREAD; ++j) {
        const size_t fb = (size_t)(f[j] >= 0 ? f[j] : 0) * 3;
        c0[j] = __ldg(g_face_colors + fb + 0);
        c1[j] = __ldg(g_face_colors + fb + 1);
        c2[j] = __ldg(g_face_colors + fb + 2);
    }

    // 4) Weighted sum (w.w contributions vanish via the zero pad / masking).
    float o[PIX_PER_THREAD * 3];
#pragma unroll
    for (int j = 0; j < PIX_PER_THREAD; ++j) {
        const float wx = w[j].x, wy = w[j].y, wz = w[j].z;
        o[j * 3 + 0] = wx * c0[j].x + wy * c1[j].x + wz * c2[j].x;
        o[j * 3 + 1] = wx * c0[j].y + wy * c1[j].y + wz * c2[j].y;
        o[j * 3 + 2] = wx * c0[j].z + wy * c1[j].z + wz * c2[j].z;
    }

    // 5) Store 12 contiguous floats -> 3x STG.128, streaming.
    float* ob = out + (size_t)p0 * 3;
    if (full) {
        float4* o4 = reinterpret_cast<float4*>(ob);
        __stcs(o4 + 0, make_float4(o[0], o[1],  o[2],  o[3]));
        __stcs(o4 + 1, make_float4(o[4], o[5],  o[6],  o[7]));
        __stcs(o4 + 2, make_float4(o[8], o[9],  o[10], o[11]));
    } else {
#pragma unroll
        for (int j = 0; j < PIX_PER_THREAD; ++j) {
            const int p = p0 + j;
            if (p < npix) {
                ob[j * 3 + 0] = o[j * 3 + 0];
                ob[j * 3 + 1] = o[j * 3 + 1];
                ob[j * 3 + 2] = o[j * 3 + 2];
            }
        }
    }
}

extern "C" void kernel_launch(void* const* d_in, const int* in_sizes, int n_in,
                              void* d_out, int out_size)
{
    const int*   pix_to_face = (const int*)  d_in[0];
    const float* bary        = (const float*)d_in[1];
    const int*   faces       = (const int*)  d_in[2];
    const float* verts       = (const float*)d_in[3];
    float*       out         = (float*)      d_out;

    // Prepro: gather per-face vertex colors into padded float4 table.
    int nfv = in_sizes[2];                       // F * 3
    if (nfv > F_MAX * 3) nfv = F_MAX * 3;        // scratch capacity guard
    {
        const int block = 256;
        const int grid  = (nfv + block - 1) / block;
        build_face_colors<<<grid, block>>>(faces, verts, nfv);
    }

    // Main shader.
    const int npix     = in_sizes[0] / KSAMP;    // N*H*W
    const int nthreads = (npix + PIX_PER_THREAD - 1) / PIX_PER_THREAD;
    const int block    = 256;
    const int grid     = (nthreads + block - 1) / block;
    unlit_shader_kernel<<<grid, block>>>(pix_to_face, bary, out, npix);
}

// round 4
// speedup vs baseline: 1.4889x; 1.2109x over previous
#include <cuda_runtime.h>
#include <cuda_fp16.h>
#include <cstddef>
#include <cstdint>

// Problem constants (from reference):
//   pix_to_face : [N,H,W,K]      int32,  K = 4
//   bary_coords : [N,H,W,K,3]    float32
//   faces       : [F,3]          int32,  F = 200000
//   verts_colors: [V,3]          float32, V = 100000
//   output      : [N,H,W,3]      float32  (sample K=0 only)

#define KSAMP 4
#define PIX_PER_THREAD 4
#define F_MAX 200000

// Bit-cast helpers (the CUDA fp16 API has no __half2<->uint casts).
__device__ __forceinline__ uint32_t h2_as_u32(__half2 h) {
    return *reinterpret_cast<uint32_t*>(&h);
}
__device__ __forceinline__ __half2 u32_as_h2(uint32_t u) {
    return *reinterpret_cast<__half2*>(&u);
}

// 32B-aligned per-face record: 9 fp16 colors (c0.xyz c1.xyz c2.xyz) + pad.
// 200000 * 32B = 6.4 MB -> comfortably L2-resident.
struct alignas(32) FaceRec {
    uint32_t u[8];   // u[0]=(h0,h1) u[1]=(h2,h3) u[2]=(h4,h5) u[3]=(h6,h7) u[4]=(h8,pad)
};
__device__ FaceRec g_face_tab[F_MAX];

// ---------------------------------------------------------------------------
// Prepro: one thread per face. Gather 3 vertex colors, pack to fp16, store 32B.
// ---------------------------------------------------------------------------
__global__ void __launch_bounds__(256)
build_face_tab(const int*   __restrict__ faces,
               const float* __restrict__ verts,
               int nfaces)
{
    const int i = blockIdx.x * blockDim.x + threadIdx.x;
    if (i >= nfaces) return;

    const int v0 = __ldg(faces + (size_t)i * 3 + 0);
    const int v1 = __ldg(faces + (size_t)i * 3 + 1);
    const int v2 = __ldg(faces + (size_t)i * 3 + 2);

    float c[9];
#pragma unroll
    for (int k = 0; k < 3; ++k) c[0 + k] = __ldg(verts + (size_t)v0 * 3 + k);
#pragma unroll
    for (int k = 0; k < 3; ++k) c[3 + k] = __ldg(verts + (size_t)v1 * 3 + k);
#pragma unroll
    for (int k = 0; k < 3; ++k) c[6 + k] = __ldg(verts + (size_t)v2 * 3 + k);

    FaceRec r;
    r.u[0] = h2_as_u32(__floats2half2_rn(c[0], c[1]));
    r.u[1] = h2_as_u32(__floats2half2_rn(c[2], c[3]));
    r.u[2] = h2_as_u32(__floats2half2_rn(c[4], c[5]));
    r.u[3] = h2_as_u32(__floats2half2_rn(c[6], c[7]));
    r.u[4] = h2_as_u32(__floats2half2_rn(c[8], 0.0f));
    r.u[5] = 0u; r.u[6] = 0u; r.u[7] = 0u;

    // Two 16B stores (contiguous 32B, coalesced).
    uint4* dst = reinterpret_cast<uint4*>(&g_face_tab[i]);
    dst[0] = make_uint4(r.u[0], r.u[1], r.u[2], r.u[3]);
    dst[1] = make_uint4(r.u[4], r.u[5], r.u[6], r.u[7]);
}

// 256-bit global load (Blackwell LDG.E.256). addr must be 32B-aligned.
__device__ __forceinline__ void ldg256(const void* p,
                                       uint32_t& a0, uint32_t& a1, uint32_t& a2, uint32_t& a3,
                                       uint32_t& a4, uint32_t& a5, uint32_t& a6, uint32_t& a7)
{
    asm volatile("ld.global.v8.b32 {%0,%1,%2,%3,%4,%5,%6,%7}, [%8];"
                 : "=r"(a0), "=r"(a1), "=r"(a2), "=r"(a3),
                   "=r"(a4), "=r"(a5), "=r"(a6), "=r"(a7)
                 : "l"(p));
}

// ---------------------------------------------------------------------------
// Main shader: 4 pixels/thread, ONE 256-bit gather per pixel.
// ---------------------------------------------------------------------------
__global__ void __launch_bounds__(256)
unlit_shader_kernel(const int*   __restrict__ pix_to_face,
                    const float* __restrict__ bary,
                    float*       __restrict__ out,
                    int npix)
{
    const int t  = blockIdx.x * blockDim.x + threadIdx.x;
    const int p0 = t * PIX_PER_THREAD;
    if (p0 >= npix) return;
    const bool full = (p0 + PIX_PER_THREAD <= npix);

    // 1) Face indices (vectorized int4, coalesced; sample K=0 in .x).
    int f[PIX_PER_THREAD];
#pragma unroll
    for (int j = 0; j < PIX_PER_THREAD; ++j) {
        const int p = p0 + j;
        if (full || p < npix) {
            const int4 s = __ldcs(reinterpret_cast<const int4*>(pix_to_face) + p);
            f[j] = s.x;
        } else {
            f[j] = -1;
        }
    }

    // 2) Barycentric weights (float4 @ 48B stride, 16B-aligned, streaming).
    float4 w[PIX_PER_THREAD];
#pragma unroll
    for (int j = 0; j < PIX_PER_THREAD; ++j) {
        const int p = p0 + j;
        w[j] = (f[j] >= 0)
             ? __ldcs(reinterpret_cast<const float4*>(bary + (size_t)p * (KSAMP * 3)))
             : make_float4(0.f, 0.f, 0.f, 0.f);
    }

    // 3) One 256-bit gather per pixel from the L2-resident fp16 table.
    uint32_t g[PIX_PER_THREAD][8];
#pragma unroll
    for (int j = 0; j < PIX_PER_THREAD; ++j) {
        const int fi = (f[j] >= 0) ? f[j] : 0;
        ldg256(&g_face_tab[fi],
               g[j][0], g[j][1], g[j][2], g[j][3],
               g[j][4], g[j][5], g[j][6], g[j][7]);
    }

    // 4) Unpack fp16 -> fp32, barycentric weighted sum.
    float o[PIX_PER_THREAD * 3];
#pragma unroll
    for (int j = 0; j < PIX_PER_THREAD; ++j) {
        const float2 h01 = __half22float2(u32_as_h2(g[j][0])); // c0.x c0.y
        const float2 h23 = __half22float2(u32_as_h2(g[j][1])); // c0.z c1.x
        const float2 h45 = __half22float2(u32_as_h2(g[j][2])); // c1.y c1.z
        const float2 h67 = __half22float2(u32_as_h2(g[j][3])); // c2.x c2.y
        const float2 h8_ = __half22float2(u32_as_h2(g[j][4])); // c2.z pad
        const float wx = w[j].x, wy = w[j].y, wz = w[j].z;
        o[j * 3 + 0] = wx * h01.x + wy * h23.y + wz * h67.x;
        o[j * 3 + 1] = wx * h01.y + wy * h45.x + wz * h67.y;
        o[j * 3 + 2] = wx * h23.x + wy * h45.y + wz * h8_.x;
    }

    // 5) Store 12 contiguous floats -> 3x STG.128, streaming.
    float* ob = out + (size_t)p0 * 3;
    if (full) {
        float4* o4 = reinterpret_cast<float4*>(ob);
        __stcs(o4 + 0, make_float4(o[0], o[1],  o[2],  o[3]));
        __stcs(o4 + 1, make_float4(o[4], o[5],  o[6],  o[7]));
        __stcs(o4 + 2, make_float4(o[8], o[9],  o[10], o[11]));
    } else {
#pragma unroll
        for (int j = 0; j < PIX_PER_THREAD; ++j) {
            const int p = p0 + j;
            if (p < npix) {
                ob[j * 3 + 0] = o[j * 3 + 0];
                ob[j * 3 + 1] = o[j * 3 + 1];
                ob[j * 3 + 2] = o[j * 3 + 2];
            }
        }
    }
}

extern "C" void kernel_launch(void* const* d_in, const int* in_sizes, int n_in,
                              void* d_out, int out_size)
{
    const int*   pix_to_face = (const int*)  d_in[0];
    const float* bary        = (const float*)d_in[1];
    const int*   faces       = (const int*)  d_in[2];
    const float* verts       = (const float*)d_in[3];
    float*       out         = (float*)      d_out;

    // Prepro: one thread per face.
    int nfaces = in_sizes[2] / 3;
    if (nfaces > F_MAX) nfaces = F_MAX;
    {
        const int block = 256;
        const int grid  = (nfaces + block - 1) / block;
        build_face_tab<<<grid, block>>>(faces, verts, nfaces);
    }

    // Main shader.
    const int npix     = in_sizes[0] / KSAMP;    // N*H*W
    const int nthreads = (npix + PIX_PER_THREAD - 1) / PIX_PER_THREAD;
    const int block    = 256;
    const int grid     = (nthreads + block - 1) / block;
    unlit_shader_kernel<<<grid, block>>>(pix_to_face, bary, out, npix);
}